// round 11
// baseline (speedup 1.0000x reference)
#include <cuda_runtime.h>
#include <cstdint>

#define IMG_W    512
#define OUTW     502
#define NPLANE   48
#define IN_COLS  136
#define OUT_COLS 126
#define OUT_ROWS 16
#define IN_ROWS  26          // OUT_ROWS + 10
#define PITCH    137         // cells (16 B) per smem row; odd -> conflict-free phases
#define KS       11
#define SEGL     16          // outputs per thread in pass 2 (8 segs x 16 = 128 >= 126)
#define GX       4           // 4*126 = 504 >= 502
#define GY       32
#define NBLOCKS  (GX * GY * NPLANE)   // 6144

typedef unsigned long long u64;
typedef unsigned int       u32;

__device__ double   g_acc   = 0.0;
__device__ unsigned g_count = 0u;

// Gaussian(sigma=1.5, k=11) normalized fp32 weights
static __device__ constexpr float WT[KS] = {
    0.00102838f, 0.00759876f, 0.03600077f, 0.10936069f, 0.21300554f,
    0.26601172f,
    0.21300554f, 0.10936069f, 0.03600077f, 0.00759876f, 0.00102838f
};

__device__ __forceinline__ u64 pack2(float lo, float hi) {
    u64 r; asm("mov.b64 %0,{%1,%2};" : "=l"(r) : "f"(lo), "f"(hi)); return r;
}
__device__ __forceinline__ void unpack2(u64 v, float& lo, float& hi) {
    asm("mov.b64 {%0,%1},%2;" : "=f"(lo), "=f"(hi) : "l"(v));
}
__device__ __forceinline__ u64 fma2(u64 a, u64 b, u64 c) {
    u64 r; asm("fma.rn.f32x2 %0,%1,%2,%3;" : "=l"(r) : "l"(a), "l"(b), "l"(c)); return r;
}
__device__ __forceinline__ void sts128(u32 addr, u64 a, u64 b) {
    u32 a0, a1, b0, b1;
    asm("mov.b64 {%0,%1},%2;" : "=r"(a0), "=r"(a1) : "l"(a));
    asm("mov.b64 {%0,%1},%2;" : "=r"(b0), "=r"(b1) : "l"(b));
    asm volatile("st.shared.v4.b32 [%0],{%1,%2,%3,%4};"
                 :: "r"(addr), "r"(a0), "r"(a1), "r"(b0), "r"(b1));
}
__device__ __forceinline__ void lds128(u32 addr, u64& a, u64& b) {
    u32 a0, a1, b0, b1;
    asm volatile("ld.shared.v4.b32 {%0,%1,%2,%3},[%4];"
                 : "=r"(a0), "=r"(a1), "=r"(b0), "=r"(b1) : "r"(addr));
    asm("mov.b64 %0,{%1,%2};" : "=l"(a) : "r"(a0), "r"(a1));
    asm("mov.b64 %0,{%1,%2};" : "=l"(b) : "r"(b0), "r"(b1));
}

extern __shared__ unsigned char smem_raw[];   // OUT_ROWS * PITCH * 16 bytes of cells

// ---- Pass 1: vertical sliding blur of {(x,y),(x2+y2,xy)}; thread = one column ----
template <bool GUARD>
__device__ __forceinline__ void pass1_body(const float* __restrict__ xcol,
                                           const float* __restrict__ ycol,
                                           int r0, bool colok, u32 cell_addr,
                                           const u64* wp) {
    u64 a01[KS], a23[KS];
    #pragma unroll
    for (int j = 0; j < KS; j++) { a01[j] = 0ull; a23[j] = 0ull; }

    #pragma unroll
    for (int i = 0; i < IN_ROWS; i++) {
        const int gr = r0 + i;
        float vx, vy;
        if (GUARD) {
            const bool ok = colok && (gr < IMG_W);
            vx = ok ? __ldg(xcol + gr * IMG_W) : 0.f;
            vy = ok ? __ldg(ycol + gr * IMG_W) : 0.f;
        } else {
            vx = __ldg(xcol + gr * IMG_W);
            vy = __ldg(ycol + gr * IMG_W);
        }
        u64 v01 = pack2(vx, vy);
        u64 v23 = pack2(fmaf(vx, vx, vy * vy), vx * vy);

        const int jlo = (10 - i) > 0 ? (10 - i) : 0;
        const int jhi = (IN_ROWS - 1 - i) < 10 ? (IN_ROWS - 1 - i) : 10;
        #pragma unroll
        for (int j = 0; j < KS; j++) {
            if (j >= jlo && j <= jhi) {
                a01[j] = fma2(wp[10 - j], v01, a01[j]);
                a23[j] = fma2(wp[10 - j], v23, a23[j]);
            }
        }
        if (i >= 10) {
            sts128(cell_addr + (i - 10) * (PITCH * 16), a01[0], a23[0]);
        }
        #pragma unroll
        for (int j = 0; j < KS - 1; j++) { a01[j] = a01[j + 1]; a23[j] = a23[j + 1]; }
        a01[KS - 1] = 0ull; a23[KS - 1] = 0ull;
    }
}

// ---- Pass 2: horizontal sliding blur + SSIM; thread = (row, segment) ----
template <bool GUARD>
__device__ __forceinline__ float pass2_body(u32 rowaddr, int segc, bool rowok,
                                            int c0, const u64* wp) {
    u64 b01[KS], b23[KS];
    #pragma unroll
    for (int j = 0; j < KS; j++) { b01[j] = 0ull; b23[j] = 0ull; }

    float acc = 0.f;
    #pragma unroll
    for (int s = 0; s < SEGL + 10; s++) {
        int col = segc + s;
        if (col > IN_COLS - 1) col = IN_COLS - 1;   // clamp (feeds only dead outputs)
        u64 l01, l23;
        lds128(rowaddr + col * 16, l01, l23);

        const int jlo = (10 - s) > 0 ? (10 - s) : 0;
        const int jhi = (SEGL + 9 - s) < 10 ? (SEGL + 9 - s) : 10;
        #pragma unroll
        for (int j = 0; j < KS; j++) {
            if (j >= jlo && j <= jhi) {
                b01[j] = fma2(wp[10 - j], l01, b01[j]);
                b23[j] = fma2(wp[10 - j], l23, b23[j]);
            }
        }
        if (s >= 10) {
            const int lout = segc + (s - 10);
            bool ok = (lout < OUT_COLS);
            if (GUARD) ok = ok && rowok && ((c0 + lout) < OUTW);
            if (ok) {
                float mux, muy, sxy, exy;
                unpack2(b01[0], mux, muy);
                unpack2(b23[0], sxy, exy);
                float mux2 = mux * mux;
                float muy2 = muy * muy;
                float muxy = mux * muy;
                float cov  = exy - muxy;
                float t    = mux2 + muy2;
                float A    = fmaf(2.f, muxy, 1e-4f);
                float B    = fmaf(2.f, cov,  9e-4f);
                float D1   = t + 1e-4f;
                float D2   = (sxy - t) + 9e-4f;
                acc += __fdividef(A * B, D1 * D2);
            }
        }
        #pragma unroll
        for (int j = 0; j < KS - 1; j++) { b01[j] = b01[j + 1]; b23[j] = b23[j + 1]; }
        b01[KS - 1] = 0ull; b23[KS - 1] = 0ull;
    }
    return acc;
}

__launch_bounds__(128)
__global__ void ssim_kernel(const float* __restrict__ X, const float* __restrict__ Y,
                            float* __restrict__ out) {
    __shared__ float warpsums[4];
    const u32 sbase = (u32)__cvta_generic_to_shared(smem_raw);

    const int tid   = threadIdx.x;
    const int plane = blockIdx.z;
    const int c0    = blockIdx.x * OUT_COLS;
    const int r0    = blockIdx.y * OUT_ROWS;
    const bool edge = (blockIdx.x == GX - 1) || (blockIdx.y == GY - 1);

    const float* __restrict__ xp = X + (size_t)plane * IMG_W * IMG_W;
    const float* __restrict__ yp = Y + (size_t)plane * IMG_W * IMG_W;

    u64 wp[KS];
    #pragma unroll
    for (int k = 0; k < KS; k++) wp[k] = pack2(WT[k], WT[k]);

    // ============ Pass 1 ============
    {
        const int  c     = tid;                     // 0..127 (col 0..127)
        // cover IN_COLS=136 columns with 128 threads: threads 0..7 do 2 columns
        const u32  cell_addr = sbase + c * 16;
        const int  gc = c0 + c;
        if (!edge) {
            pass1_body<false>(xp + gc, yp + gc, r0, true, cell_addr, wp);
            if (c < IN_COLS - 128) {
                const int c2 = c + 128;
                pass1_body<false>(xp + c0 + c2, yp + c0 + c2, r0, true, sbase + c2 * 16, wp);
            }
        } else {
            pass1_body<true>(xp + gc, yp + gc, r0, gc < IMG_W, cell_addr, wp);
            if (c < IN_COLS - 128) {
                const int c2 = c + 128;
                const int gc2 = c0 + c2;
                pass1_body<true>(xp + gc2, yp + gc2, r0, gc2 < IMG_W, sbase + c2 * 16, wp);
            }
        }
    }

    __syncthreads();

    // ============ Pass 2 ============
    float acc;
    {
        const int  r     = tid & 15;                // smem row (0..15)
        const int  seg   = tid >> 4;                // 0..7
        const int  segc  = seg * SEGL;              // 0,16,...,112
        const bool rowok = (r0 + r) < OUTW;
        const u32  rowaddr = sbase + r * (PITCH * 16);
        if (!edge) acc = pass2_body<false>(rowaddr, segc, true,  c0, wp);
        else       acc = pass2_body<true >(rowaddr, segc, rowok, c0, wp);
    }

    // ============ Block reduce -> global atomic -> last-block finalize ============
    #pragma unroll
    for (int off = 16; off > 0; off >>= 1)
        acc += __shfl_down_sync(0xffffffffu, acc, off);
    if ((tid & 31) == 0) warpsums[tid >> 5] = acc;
    __syncthreads();
    if (tid == 0) {
        float blocksum = (warpsums[0] + warpsums[1]) + (warpsums[2] + warpsums[3]);
        atomicAdd(&g_acc, (double)blocksum);
        __threadfence();
        unsigned prev = atomicAdd(&g_count, 1u);
        if (prev == NBLOCKS - 1) {                  // last block finalizes + resets
            double total = atomicAdd(&g_acc, 0.0);  // coherent read
            const double n = (double)NPLANE * (double)OUTW * (double)OUTW;
            out[0] = (float)(1.0 - total / n);
            g_acc   = 0.0;                          // restore invariant for next replay
            g_count = 0u;
        }
    }
}

extern "C" void kernel_launch(void* const* d_in, const int* in_sizes, int n_in,
                              void* d_out, int out_size) {
    const float* x = (const float*)d_in[0];
    const float* y = (const float*)d_in[1];
    float* out = (float*)d_out;

    const int smem_bytes = OUT_ROWS * PITCH * 16;   // 35,072 B
    cudaFuncSetAttribute(ssim_kernel, cudaFuncAttributeMaxDynamicSharedMemorySize, smem_bytes);

    dim3 grid(GX, GY, NPLANE);   // 4 x 32 x 48 = 6144 blocks
    ssim_kernel<<<grid, 128, smem_bytes>>>(x, y, out);
}

// round 14
// speedup vs baseline: 1.1994x; 1.1994x over previous
#include <cuda_runtime.h>
#include <cstdint>

#define IMG_W    512
#define OUTW     502
#define NPLANE   48
#define IN_COLS  111
#define OUT_COLS 101
#define OUT_ROWS 16
#define IN_ROWS  26          // OUT_ROWS + 10
#define PITCH    111         // cells (16 B) per smem row; odd -> conflict-free phases
#define KS       11
#define SEGL     13          // outputs per thread in pass 2 (8 segs x 13 = 104 >= 101)
#define GX       5           // 5*101 = 505 >= 502
#define GY       32
#define NBLOCKS  (GX * GY * NPLANE)   // 7680

typedef unsigned long long u64;
typedef unsigned int       u32;

__device__ double   g_total_acc = 0.0;
__device__ unsigned g_done_cnt  = 0u;

// Gaussian(sigma=1.5, k=11) normalized fp32 weights
static __device__ constexpr float WT[KS] = {
    0.00102838f, 0.00759876f, 0.03600077f, 0.10936069f, 0.21300554f,
    0.26601172f,
    0.21300554f, 0.10936069f, 0.03600077f, 0.00759876f, 0.00102838f
};

__device__ __forceinline__ u64 pack2(float lo, float hi) {
    u64 r; asm("mov.b64 %0,{%1,%2};" : "=l"(r) : "f"(lo), "f"(hi)); return r;
}
__device__ __forceinline__ void unpack2(u64 v, float& lo, float& hi) {
    asm("mov.b64 {%0,%1},%2;" : "=f"(lo), "=f"(hi) : "l"(v));
}
__device__ __forceinline__ u64 fma2(u64 a, u64 b, u64 c) {
    u64 r; asm("fma.rn.f32x2 %0,%1,%2,%3;" : "=l"(r) : "l"(a), "l"(b), "l"(c)); return r;
}
__device__ __forceinline__ void sts128(u32 addr, u64 a, u64 b) {
    u32 a0, a1, b0, b1;
    asm("mov.b64 {%0,%1},%2;" : "=r"(a0), "=r"(a1) : "l"(a));
    asm("mov.b64 {%0,%1},%2;" : "=r"(b0), "=r"(b1) : "l"(b));
    asm volatile("st.shared.v4.b32 [%0],{%1,%2,%3,%4};"
                 :: "r"(addr), "r"(a0), "r"(a1), "r"(b0), "r"(b1));
}
__device__ __forceinline__ void lds128(u32 addr, u64& a, u64& b) {
    u32 a0, a1, b0, b1;
    asm volatile("ld.shared.v4.b32 {%0,%1,%2,%3},[%4];"
                 : "=r"(a0), "=r"(a1), "=r"(b0), "=r"(b1) : "r"(addr));
    asm("mov.b64 %0,{%1,%2};" : "=l"(a) : "r"(a0), "r"(a1));
    asm("mov.b64 %0,{%1,%2};" : "=l"(b) : "r"(b0), "r"(b1));
}

// dynamic smem: OUT_ROWS*PITCH 16B cells, then 4 floats of warpsums
extern __shared__ unsigned char smem_raw[];

// ---- Pass 1: vertical sliding blur of {(x,y),(x2+y2,xy)}; thread = one column ----
template <bool GUARD>
__device__ __forceinline__ void pass1_body(const float* __restrict__ xcol,
                                           const float* __restrict__ ycol,
                                           int r0, bool colok, u32 cell_addr,
                                           const u64* wp) {
    u64 a01[KS], a23[KS];
    #pragma unroll
    for (int j = 0; j < KS; j++) { a01[j] = 0ull; a23[j] = 0ull; }

    #pragma unroll
    for (int i = 0; i < IN_ROWS; i++) {
        const int gr = r0 + i;
        float vx, vy;
        if (GUARD) {
            const bool ok = colok && (gr < IMG_W);
            vx = ok ? xcol[gr * IMG_W] : 0.f;
            vy = ok ? ycol[gr * IMG_W] : 0.f;
        } else {
            vx = xcol[gr * IMG_W];
            vy = ycol[gr * IMG_W];
        }
        const u64 v01 = pack2(vx, vy);
        const u64 v23 = pack2(fmaf(vx, vx, vy * vy), vx * vy);

        const int jlo = (10 - i) > 0 ? (10 - i) : 0;
        const int jhi = (IN_ROWS - 1 - i) < 10 ? (IN_ROWS - 1 - i) : 10;
        #pragma unroll
        for (int j = 0; j < KS; j++) {
            if (j >= jlo && j <= jhi) {
                a01[j] = fma2(wp[10 - j], v01, a01[j]);
                a23[j] = fma2(wp[10 - j], v23, a23[j]);
            }
        }
        if (i >= 10) {
            sts128(cell_addr + (i - 10) * (PITCH * 16), a01[0], a23[0]);
        }
        #pragma unroll
        for (int j = 0; j < KS - 1; j++) { a01[j] = a01[j + 1]; a23[j] = a23[j + 1]; }
        a01[KS - 1] = 0ull; a23[KS - 1] = 0ull;
    }
}

// ---- Pass 2: horizontal sliding blur + SSIM; thread = (row, segment) ----
template <bool GUARD>
__device__ __forceinline__ float pass2_body(u32 rowaddr, int segc, bool rowok,
                                            int c0, const u64* wp) {
    u64 b01[KS], b23[KS];
    #pragma unroll
    for (int j = 0; j < KS; j++) { b01[j] = 0ull; b23[j] = 0ull; }

    float acc = 0.f;
    #pragma unroll
    for (int s = 0; s < SEGL + 10; s++) {
        int col = segc + s;
        if (col > IN_COLS - 1) col = IN_COLS - 1;   // clamp (feeds only dead outputs)
        u64 l01, l23;
        lds128(rowaddr + col * 16, l01, l23);

        const int jlo = (10 - s) > 0 ? (10 - s) : 0;
        const int jhi = (SEGL + 9 - s) < 10 ? (SEGL + 9 - s) : 10;
        #pragma unroll
        for (int j = 0; j < KS; j++) {
            if (j >= jlo && j <= jhi) {
                b01[j] = fma2(wp[10 - j], l01, b01[j]);
                b23[j] = fma2(wp[10 - j], l23, b23[j]);
            }
        }
        if (s >= 10) {
            const int lout = segc + (s - 10);
            bool ok = (lout < OUT_COLS);
            if (GUARD) ok = ok && rowok && ((c0 + lout) < OUTW);
            if (ok) {
                float mux, muy, sxy, exy;
                unpack2(b01[0], mux, muy);
                unpack2(b23[0], sxy, exy);
                const float mux2 = mux * mux;
                const float muy2 = muy * muy;
                const float muxy = mux * muy;
                const float cov  = exy - muxy;
                const float t    = mux2 + muy2;
                const float A    = fmaf(2.f, muxy, 1e-4f);
                const float B    = fmaf(2.f, cov,  9e-4f);
                const float D1   = t + 1e-4f;
                const float D2   = (sxy - t) + 9e-4f;
                acc += __fdividef(A * B, D1 * D2);
            }
        }
        #pragma unroll
        for (int j = 0; j < KS - 1; j++) { b01[j] = b01[j + 1]; b23[j] = b23[j + 1]; }
        b01[KS - 1] = 0ull; b23[KS - 1] = 0ull;
    }
    return acc;
}

__launch_bounds__(128)
__global__ void ssim_fused_kernel(const float* __restrict__ X, const float* __restrict__ Y,
                                  float* __restrict__ out) {
    const u32 sbase = (u32)__cvta_generic_to_shared(smem_raw);
    float* warpsums = (float*)(smem_raw + OUT_ROWS * PITCH * 16);

    const int tid   = threadIdx.x;
    const int plane = blockIdx.z;
    const int c0    = blockIdx.x * OUT_COLS;
    const int r0    = blockIdx.y * OUT_ROWS;
    const bool edge = (blockIdx.x == GX - 1) || (blockIdx.y == GY - 1);

    const float* __restrict__ xp = X + (size_t)plane * IMG_W * IMG_W;
    const float* __restrict__ yp = Y + (size_t)plane * IMG_W * IMG_W;

    u64 wp[KS];
    #pragma unroll
    for (int k = 0; k < KS; k++) wp[k] = pack2(WT[k], WT[k]);

    // ============ Pass 1: threads 0..110 own one column each ============
    if (tid < IN_COLS) {
        const int  gc = c0 + tid;
        const u32  cell_addr = sbase + tid * 16;
        if (!edge) pass1_body<false>(xp + gc, yp + gc, r0, true,       cell_addr, wp);
        else       pass1_body<true >(xp + gc, yp + gc, r0, gc < IMG_W, cell_addr, wp);
    }

    __syncthreads();

    // ============ Pass 2 ============
    float acc;
    {
        const int  r     = tid & 15;                // smem row (0..15)
        const int  segc  = (tid >> 4) * SEGL;       // 0,13,...,91
        const bool rowok = (r0 + r) < OUTW;
        const u32  rowaddr = sbase + r * (PITCH * 16);
        if (!edge) acc = pass2_body<false>(rowaddr, segc, true,  c0, wp);
        else       acc = pass2_body<true >(rowaddr, segc, rowok, c0, wp);
    }

    // ============ Block reduce -> global atomic -> last-block finalize ============
    #pragma unroll
    for (int off = 16; off > 0; off >>= 1)
        acc += __shfl_down_sync(0xffffffffu, acc, off);
    if ((tid & 31) == 0) warpsums[tid >> 5] = acc;
    __syncthreads();
    if (tid == 0) {
        const float blocksum = (warpsums[0] + warpsums[1]) + (warpsums[2] + warpsums[3]);
        atomicAdd(&g_total_acc, (double)blocksum);
        __threadfence();
        const unsigned prev = atomicAdd(&g_done_cnt, 1u);
        if (prev == NBLOCKS - 1) {                  // last block finalizes + resets
            const double total = atomicAdd(&g_total_acc, 0.0);   // coherent read
            const double n = (double)NPLANE * (double)OUTW * (double)OUTW;
            out[0] = (float)(1.0 - total / n);
            g_total_acc = 0.0;                      // restore invariant for next replay
            g_done_cnt  = 0u;
        }
    }
}

extern "C" void kernel_launch(void* const* d_in, const int* in_sizes, int n_in,
                              void* d_out, int out_size) {
    const float* x = (const float*)d_in[0];
    const float* y = (const float*)d_in[1];
    float* out = (float*)d_out;

    const int smem_bytes = OUT_ROWS * PITCH * 16 + 4 * sizeof(float);   // 28,432 B
    cudaFuncSetAttribute(ssim_fused_kernel, cudaFuncAttributeMaxDynamicSharedMemorySize, smem_bytes);

    dim3 grid(GX, GY, NPLANE);   // 5 x 32 x 48 = 7680 blocks
    ssim_fused_kernel<<<grid, 128, smem_bytes>>>(x, y, out);
}

// round 16
// speedup vs baseline: 1.2223x; 1.0191x over previous
#include <cuda_runtime.h>
#include <cstdint>

#define IMG_W    512
#define OUTW     502
#define NPLANE   48
#define IN_COLS  111
#define OUT_COLS 101
#define OUT_ROWS 16
#define IN_ROWS  26          // OUT_ROWS + 10
#define PITCH    111         // cells (16 B) per smem row; odd -> conflict-free phases
#define KS       11
#define SEGL     13          // outputs per thread in pass 2 (8 segs x 13 = 104 >= 101)
#define GX       5           // 5*101 = 505 >= 502
#define GY       32
#define NBLOCKS  (GX * GY * NPLANE)   // 7680

typedef unsigned long long u64;
typedef unsigned int       u32;

__device__ double   g_total_acc = 0.0;
__device__ unsigned g_done_cnt  = 0u;

// Gaussian(sigma=1.5, k=11) normalized fp32 weights
static __device__ constexpr float WT[KS] = {
    0.00102838f, 0.00759876f, 0.03600077f, 0.10936069f, 0.21300554f,
    0.26601172f,
    0.21300554f, 0.10936069f, 0.03600077f, 0.00759876f, 0.00102838f
};

__device__ __forceinline__ u64 pack2(float lo, float hi) {
    u64 r; asm("mov.b64 %0,{%1,%2};" : "=l"(r) : "f"(lo), "f"(hi)); return r;
}
__device__ __forceinline__ void unpack2(u64 v, float& lo, float& hi) {
    asm("mov.b64 {%0,%1},%2;" : "=f"(lo), "=f"(hi) : "l"(v));
}
__device__ __forceinline__ u64 fma2(u64 a, u64 b, u64 c) {
    u64 r; asm("fma.rn.f32x2 %0,%1,%2,%3;" : "=l"(r) : "l"(a), "l"(b), "l"(c)); return r;
}
__device__ __forceinline__ void sts128(u32 addr, u64 a, u64 b) {
    u32 a0, a1, b0, b1;
    asm("mov.b64 {%0,%1},%2;" : "=r"(a0), "=r"(a1) : "l"(a));
    asm("mov.b64 {%0,%1},%2;" : "=r"(b0), "=r"(b1) : "l"(b));
    asm volatile("st.shared.v4.b32 [%0],{%1,%2,%3,%4};"
                 :: "r"(addr), "r"(a0), "r"(a1), "r"(b0), "r"(b1));
}
__device__ __forceinline__ void lds128(u32 addr, u64& a, u64& b) {
    u32 a0, a1, b0, b1;
    asm volatile("ld.shared.v4.b32 {%0,%1,%2,%3},[%4];"
                 : "=r"(a0), "=r"(a1), "=r"(b0), "=r"(b1) : "r"(addr));
    asm("mov.b64 %0,{%1,%2};" : "=l"(a) : "r"(a0), "r"(a1));
    asm("mov.b64 %0,{%1,%2};" : "=l"(b) : "r"(b0), "r"(b1));
}

// dynamic smem: OUT_ROWS*PITCH 16B cells, then 4 floats of warpsums
extern __shared__ unsigned char smem_raw[];

// ---- Pass 1: vertical sliding blur of {(x,y),(x2+y2,xy)}; thread = one column ----
template <bool GUARD>
__device__ __forceinline__ void pass1_body(const float* __restrict__ xcol,
                                           const float* __restrict__ ycol,
                                           int r0, bool colok, u32 cell_addr,
                                           const u64* wp) {
    u64 a01[KS], a23[KS];
    #pragma unroll
    for (int j = 0; j < KS; j++) { a01[j] = 0ull; a23[j] = 0ull; }

    #pragma unroll
    for (int i = 0; i < IN_ROWS; i++) {
        const int gr = r0 + i;
        float vx, vy;
        if (GUARD) {
            const bool ok = colok && (gr < IMG_W);
            vx = ok ? xcol[gr * IMG_W] : 0.f;
            vy = ok ? ycol[gr * IMG_W] : 0.f;
        } else {
            vx = xcol[gr * IMG_W];
            vy = ycol[gr * IMG_W];
        }
        const u64 v01 = pack2(vx, vy);
        const u64 v23 = pack2(fmaf(vx, vx, vy * vy), vx * vy);

        const int jlo = (10 - i) > 0 ? (10 - i) : 0;
        const int jhi = (IN_ROWS - 1 - i) < 10 ? (IN_ROWS - 1 - i) : 10;
        #pragma unroll
        for (int j = 0; j < KS; j++) {
            if (j >= jlo && j <= jhi) {
                a01[j] = fma2(wp[10 - j], v01, a01[j]);
                a23[j] = fma2(wp[10 - j], v23, a23[j]);
            }
        }
        if (i >= 10) {
            sts128(cell_addr + (i - 10) * (PITCH * 16), a01[0], a23[0]);
        }
        #pragma unroll
        for (int j = 0; j < KS - 1; j++) { a01[j] = a01[j + 1]; a23[j] = a23[j + 1]; }
        a01[KS - 1] = 0ull; a23[KS - 1] = 0ull;
    }
}

// ---- Pass 2: horizontal sliding blur + SSIM; thread = (row, segment) ----
template <bool GUARD>
__device__ __forceinline__ float pass2_body(u32 rowaddr, int segc, bool rowok,
                                            int c0, const u64* wp) {
    u64 b01[KS], b23[KS];
    #pragma unroll
    for (int j = 0; j < KS; j++) { b01[j] = 0ull; b23[j] = 0ull; }

    float acc = 0.f;
    #pragma unroll
    for (int s = 0; s < SEGL + 10; s++) {
        int col = segc + s;
        if (col > IN_COLS - 1) col = IN_COLS - 1;   // clamp (feeds only dead outputs)
        u64 l01, l23;
        lds128(rowaddr + col * 16, l01, l23);

        const int jlo = (10 - s) > 0 ? (10 - s) : 0;
        const int jhi = (SEGL + 9 - s) < 10 ? (SEGL + 9 - s) : 10;
        #pragma unroll
        for (int j = 0; j < KS; j++) {
            if (j >= jlo && j <= jhi) {
                b01[j] = fma2(wp[10 - j], l01, b01[j]);
                b23[j] = fma2(wp[10 - j], l23, b23[j]);
            }
        }
        if (s >= 10) {
            const int lout = segc + (s - 10);
            bool ok = (lout < OUT_COLS);
            if (GUARD) ok = ok && rowok && ((c0 + lout) < OUTW);
            if (ok) {
                float mux, muy, sxy, exy;
                unpack2(b01[0], mux, muy);
                unpack2(b23[0], sxy, exy);
                const float mux2 = mux * mux;
                const float muy2 = muy * muy;
                const float muxy = mux * muy;
                const float cov  = exy - muxy;
                const float t    = mux2 + muy2;
                const float A    = fmaf(2.f, muxy, 1e-4f);
                const float B    = fmaf(2.f, cov,  9e-4f);
                const float D1   = t + 1e-4f;
                const float D2   = (sxy - t) + 9e-4f;
                acc += __fdividef(A * B, D1 * D2);
            }
        }
        #pragma unroll
        for (int j = 0; j < KS - 1; j++) { b01[j] = b01[j + 1]; b23[j] = b23[j + 1]; }
        b01[KS - 1] = 0ull; b23[KS - 1] = 0ull;
    }
    return acc;
}

__launch_bounds__(128, 8)
__global__ void ssim_fused_v2_kernel(const float* __restrict__ X, const float* __restrict__ Y,
                                     float* __restrict__ out) {
    const u32 sbase = (u32)__cvta_generic_to_shared(smem_raw);
    float* warpsums = (float*)(smem_raw + OUT_ROWS * PITCH * 16);

    const int tid   = threadIdx.x;
    const int plane = blockIdx.z;
    const int c0    = blockIdx.x * OUT_COLS;
    const int r0    = blockIdx.y * OUT_ROWS;
    const bool edge = (blockIdx.x == GX - 1) || (blockIdx.y == GY - 1);

    const float* __restrict__ xp = X + (size_t)plane * IMG_W * IMG_W;
    const float* __restrict__ yp = Y + (size_t)plane * IMG_W * IMG_W;

    u64 wp[KS];
    #pragma unroll
    for (int k = 0; k < KS; k++) wp[k] = pack2(WT[k], WT[k]);

    // ============ Pass 1: threads 0..110 own one column each ============
    if (tid < IN_COLS) {
        const int  gc = c0 + tid;
        const u32  cell_addr = sbase + tid * 16;
        if (!edge) pass1_body<false>(xp + gc, yp + gc, r0, true,       cell_addr, wp);
        else       pass1_body<true >(xp + gc, yp + gc, r0, gc < IMG_W, cell_addr, wp);
    }

    __syncthreads();

    // ============ Pass 2 ============
    float acc;
    {
        const int  r     = tid & 15;                // smem row (0..15)
        const int  segc  = (tid >> 4) * SEGL;       // 0,13,...,91
        const bool rowok = (r0 + r) < OUTW;
        const u32  rowaddr = sbase + r * (PITCH * 16);
        if (!edge) acc = pass2_body<false>(rowaddr, segc, true,  c0, wp);
        else       acc = pass2_body<true >(rowaddr, segc, rowok, c0, wp);
    }

    // ============ Block reduce -> global atomic -> last-block finalize ============
    #pragma unroll
    for (int off = 16; off > 0; off >>= 1)
        acc += __shfl_down_sync(0xffffffffu, acc, off);
    if ((tid & 31) == 0) warpsums[tid >> 5] = acc;
    __syncthreads();
    if (tid == 0) {
        const float blocksum = (warpsums[0] + warpsums[1]) + (warpsums[2] + warpsums[3]);
        atomicAdd(&g_total_acc, (double)blocksum);
        __threadfence();
        const unsigned prev = atomicAdd(&g_done_cnt, 1u);
        if (prev == NBLOCKS - 1) {                  // last block finalizes + resets
            const double total = atomicAdd(&g_total_acc, 0.0);   // coherent read
            const double n = (double)NPLANE * (double)OUTW * (double)OUTW;
            out[0] = (float)(1.0 - total / n);
            g_total_acc = 0.0;                      // restore invariant for next replay
            g_done_cnt  = 0u;
        }
    }
}

extern "C" void kernel_launch(void* const* d_in, const int* in_sizes, int n_in,
                              void* d_out, int out_size) {
    const float* x = (const float*)d_in[0];
    const float* y = (const float*)d_in[1];
    float* out = (float*)d_out;

    const int smem_bytes = OUT_ROWS * PITCH * 16 + 4 * sizeof(float);   // 28,432 B
    cudaFuncSetAttribute(ssim_fused_v2_kernel, cudaFuncAttributeMaxDynamicSharedMemorySize, smem_bytes);
    // Max smem carveout so residency isn't capped below 8 blocks/SM.
    cudaFuncSetAttribute(ssim_fused_v2_kernel, cudaFuncAttributePreferredSharedMemoryCarveout, 100);

    dim3 grid(GX, GY, NPLANE);   // 5 x 32 x 48 = 7680 blocks
    ssim_fused_v2_kernel<<<grid, 128, smem_bytes>>>(x, y, out);
}